// round 10
// baseline (speedup 1.0000x reference)
#include <cuda_runtime.h>
#include <cuda_bf16.h>
#include <math.h>
#include <stdint.h>

#define NB   8
#define CDIM 256
#define CKD  64
#define NN   4096

// ---------------------------------------------------------------------------
// Scratch (allocation-free rule: __device__ globals). All split bf16 hi/lo.
// ---------------------------------------------------------------------------
__device__ __nv_bfloat16 g_xh[NB * CDIM * NN], g_xl[NB * CDIM * NN];
__device__ __nv_bfloat16 g_Qh[NB * CKD  * NN], g_Ql[NB * CKD  * NN];
__device__ __nv_bfloat16 g_Kh[NB * CKD  * NN], g_Kl[NB * CKD  * NN];
__device__ __nv_bfloat16 g_Vh[NB * CDIM * NN], g_Vl[NB * CDIM * NN];
__device__ __nv_bfloat16 g_Oh[NB * CDIM * NN], g_Ol[NB * CDIM * NN];
__device__ __nv_bfloat16 g_Wqh[CKD * CDIM],  g_Wql[CKD * CDIM];
__device__ __nv_bfloat16 g_Wkh[CKD * CDIM],  g_Wkl[CKD * CDIM];
__device__ __nv_bfloat16 g_Wvh[CDIM * CDIM], g_Wvl[CDIM * CDIM];
__device__ __nv_bfloat16 g_Wgh[CDIM * CDIM], g_Wgl[CDIM * CDIM];

// ---------------------------------------------------------------------------
// Helpers (fragment maps validated in R4/R5/R6)
// ---------------------------------------------------------------------------
__device__ __forceinline__ float elu_scaled(float x) {
    const float invN = 1.0f / 4096.0f;
    return (x > 0.f ? x : (expf(x) - 1.f)) * invN;
}
__device__ __forceinline__ void split2(float x, __nv_bfloat16& h, __nv_bfloat16& l) {
    h = __float2bfloat16(x);
    l = __float2bfloat16(x - __bfloat162float(h));
}
__device__ __forceinline__ uint32_t cvta_s(const void* p) {
    return (uint32_t)__cvta_generic_to_shared(p);
}
__device__ __forceinline__ void ldsm_x4(uint32_t* r, uint32_t addr) {
    asm volatile("ldmatrix.sync.aligned.m8n8.x4.shared.b16 {%0,%1,%2,%3},[%4];\n"
                 : "=r"(r[0]), "=r"(r[1]), "=r"(r[2]), "=r"(r[3]) : "r"(addr));
}
__device__ __forceinline__ void ldsm_x4_t(uint32_t* r, uint32_t addr) {
    asm volatile("ldmatrix.sync.aligned.m8n8.x4.trans.shared.b16 {%0,%1,%2,%3},[%4];\n"
                 : "=r"(r[0]), "=r"(r[1]), "=r"(r[2]), "=r"(r[3]) : "r"(addr));
}
__device__ __forceinline__ void mma_bf16(float* c, const uint32_t* a, const uint32_t* b) {
    asm volatile(
        "mma.sync.aligned.m16n8k16.row.col.f32.bf16.bf16.f32 "
        "{%0,%1,%2,%3},{%4,%5,%6,%7},{%8,%9},{%0,%1,%2,%3};\n"
        : "+f"(c[0]), "+f"(c[1]), "+f"(c[2]), "+f"(c[3])
        : "r"(a[0]), "r"(a[1]), "r"(a[2]), "r"(a[3]), "r"(b[0]), "r"(b[1]));
}
__device__ __forceinline__ void cp16(uint32_t saddr, const void* g) {
    asm volatile("cp.async.cg.shared.global [%0],[%1],16;\n" :: "r"(saddr), "l"(g));
}
__device__ __forceinline__ void cp_commit() {
    asm volatile("cp.async.commit_group;\n" ::: "memory");
}
template <int N> __device__ __forceinline__ void cp_wait() {
    asm volatile("cp.async.wait_group %0;\n" :: "n"(N) : "memory");
}

// ---------------------------------------------------------------------------
// Split fp32 -> bf16 hi/lo, vectorized.
// ---------------------------------------------------------------------------
__global__ __launch_bounds__(256) void split_kernel(
    const float4* __restrict__ in, __nv_bfloat162* __restrict__ oh,
    __nv_bfloat162* __restrict__ ol, int n4)
{
    int i = blockIdx.x * blockDim.x + threadIdx.x;
    if (i >= n4) return;
    float4 v = in[i];
    __nv_bfloat16 h0, l0, h1, l1, h2, l2, h3, l3;
    split2(v.x, h0, l0); split2(v.y, h1, l1);
    split2(v.z, h2, l2); split2(v.w, h3, l3);
    __nv_bfloat162 a, b;
    a.x = h0; a.y = h1; b.x = h2; b.y = h3;
    oh[i * 2] = a; oh[i * 2 + 1] = b;
    a.x = l0; a.y = l1; b.x = l2; b.y = l3;
    ol[i * 2] = a; ol[i * 2 + 1] = b;
}

// ---------------------------------------------------------------------------
// Tensor-core projection (R6-validated): Y = W X + bias
// ---------------------------------------------------------------------------
#define WLD 72
#define XLD 136

__global__ __launch_bounds__(256) void proj_mma_kernel(
    const __nv_bfloat16* __restrict__ Wh_g, const __nv_bfloat16* __restrict__ Wl_g,
    const float* __restrict__ bias,
    const __nv_bfloat16* __restrict__ Xh, const __nv_bfloat16* __restrict__ Xl,
    __nv_bfloat16* __restrict__ Yh, __nv_bfloat16* __restrict__ Yl,
    float* __restrict__ Yf, int R)
{
    extern __shared__ __nv_bfloat16 sp[];
    __nv_bfloat16* Wh   = sp;
    __nv_bfloat16* Wl   = Wh + 64 * WLD;
    __nv_bfloat16* Xbuf = Wl + 64 * WLD;

    const int b  = blockIdx.z;
    const int o0 = blockIdx.y * 64;
    const int n0 = blockIdx.x * 128;
    const int tid  = threadIdx.x;
    const int warp = tid >> 5;
    const int lane = tid & 31;

    const __nv_bfloat16* Xbh = Xh + (size_t)b * CDIM * NN;
    const __nv_bfloat16* Xbl = Xl + (size_t)b * CDIM * NN;

    const uint32_t wh_b = cvta_s(Wh), wl_b = cvta_s(Wl);
    const uint32_t x_b  = cvta_s(Xbuf);
    const uint32_t xstride = 2u * 64 * XLD * 2;

    auto issueX = [&](int kc, int buf) {
#pragma unroll
        for (int r = 0; r < 4; ++r) {
            int idx = tid + r * 256;
            int row = idx >> 4, c4 = idx & 15;
            uint32_t dh = x_b + buf * xstride + (uint32_t)(row * XLD + c4 * 8) * 2;
            cp16(dh, Xbh + (size_t)(kc * 64 + row) * NN + n0 + c4 * 8);
            cp16(dh + 64 * XLD * 2, Xbl + (size_t)(kc * 64 + row) * NN + n0 + c4 * 8);
        }
    };

    const int l7 = lane & 7, rr = lane >> 3;
    const int a_kofs = ((rr & 2) << 2) + l7;
    const int a_mofs = ((rr & 1) << 3);
    const int b_kofs = ((rr & 1) << 3) + l7;
    const int b_nofs = ((rr & 2) << 2);

    const int wo = warp >> 1;
    const int wn = warp & 1;

    float acc[8][4];
#pragma unroll
    for (int t = 0; t < 8; ++t)
#pragma unroll
        for (int e = 0; e < 4; ++e) acc[t][e] = 0.f;

    issueX(0, 0);
    cp_commit();

    for (int kc = 0; kc < 4; ++kc) {
        const int buf = kc & 1;
#pragma unroll
        for (int r = 0; r < 16; ++r) {
            int idx = tid + r * 256;
            int o = idx >> 6, cc = idx & 63;
            Wh[cc * WLD + o] = Wh_g[(size_t)(o0 + o) * CDIM + kc * 64 + cc];
            Wl[cc * WLD + o] = Wl_g[(size_t)(o0 + o) * CDIM + kc * 64 + cc];
        }
        if (kc < 3) { issueX(kc + 1, buf ^ 1); cp_commit(); cp_wait<1>(); }
        else        { cp_wait<0>(); }
        __syncthreads();

        const uint32_t xh_cur = x_b + buf * xstride;
        const uint32_t xl_cur = xh_cur + 64 * XLD * 2;

#pragma unroll
        for (int k0 = 0; k0 < 64; k0 += 16) {
            uint32_t ah[4], al[4];
            uint32_t aoff = (uint32_t)((k0 + a_kofs) * WLD + wo * 16 + a_mofs) * 2;
            ldsm_x4_t(ah, wh_b + aoff);
            ldsm_x4_t(al, wl_b + aoff);
#pragma unroll
            for (int jj = 0; jj < 4; ++jj) {
                uint32_t bh[4], bl[4];
                uint32_t boff =
                    (uint32_t)((k0 + b_kofs) * XLD + wn * 64 + jj * 16 + b_nofs) * 2;
                ldsm_x4_t(bh, xh_cur + boff);
                ldsm_x4_t(bl, xl_cur + boff);
                mma_bf16(acc[jj * 2 + 0], ah, bh + 0);
                mma_bf16(acc[jj * 2 + 0], ah, bl + 0);
                mma_bf16(acc[jj * 2 + 0], al, bh + 0);
                mma_bf16(acc[jj * 2 + 1], ah, bh + 2);
                mma_bf16(acc[jj * 2 + 1], ah, bl + 2);
                mma_bf16(acc[jj * 2 + 1], al, bh + 2);
            }
        }
        __syncthreads();
    }

    const int orow = wo * 16 + (lane >> 2);
    const float b0 = bias[o0 + orow];
    const float b1 = bias[o0 + orow + 8];
#pragma unroll
    for (int t = 0; t < 8; ++t) {
        int col = n0 + wn * 64 + t * 8 + (lane & 3) * 2;
        float v00 = acc[t][0] + b0, v01 = acc[t][1] + b0;
        float v10 = acc[t][2] + b1, v11 = acc[t][3] + b1;
        size_t i0 = ((size_t)b * R + o0 + orow) * NN + col;
        size_t i1 = ((size_t)b * R + o0 + orow + 8) * NN + col;
        if (Yf) {
            *(float2*)&Yf[i0] = make_float2(v00, v01);
            *(float2*)&Yf[i1] = make_float2(v10, v11);
        } else {
            __nv_bfloat16 h0, l0, h1, l1;
            __nv_bfloat162 th, tl;
            split2(v00, h0, l0); split2(v01, h1, l1);
            th.x = h0; th.y = h1; tl.x = l0; tl.y = l1;
            *(__nv_bfloat162*)&Yh[i0] = th;
            *(__nv_bfloat162*)&Yl[i0] = tl;
            split2(v10, h0, l0); split2(v11, h1, l1);
            th.x = h0; th.y = h1; tl.x = l0; tl.y = l1;
            *(__nv_bfloat162*)&Yh[i1] = th;
            *(__nv_bfloat162*)&Yl[i1] = tl;
        }
    }
}

// ---------------------------------------------------------------------------
// Fused attention, merged single-barrier pipeline.
// Per CTA: (b, 128 j). i tiled by 32 (128 iterations).
// Iter it: [cp.async Q(it+1), V(it)] ; S(it) ; P(it)->smem ; O(it-1) ; barrier.
// Q/P/V double-buffered; K persistent. Term-major MMA ordering.
// smem element offsets (bf16):
//   K  h/l: 0 / 8704               (64 x 136)
//   Q  [buf][h/l]: 17408 + buf*5120 + a*2560   (64 x 40)
//   P  [buf][h/l]: 27648 + buf*8704 + a*4352   (32 x 136)
//   V  [buf][h/l]: 45056 + buf*20480 + a*10240 (256 x 40)
// total 86016 el = 172032 B
// ---------------------------------------------------------------------------
#define KE(a)       ((a) * 8704)
#define QE(buf, a)  (17408 + (buf) * 5120 + (a) * 2560)
#define PE(buf, a)  (27648 + (buf) * 8704 + (a) * 4352)
#define VE(buf, a)  (45056 + (buf) * 20480 + (a) * 10240)
#define SM_ATTN_EL  86016

__global__ __launch_bounds__(512) void attn_bf16_kernel()
{
    extern __shared__ __nv_bfloat16 smb[];
    const uint32_t sb = cvta_s(smb);

    const int b    = blockIdx.y;
    const int j0g  = blockIdx.x * 128;
    const int tid  = threadIdx.x;
    const int warp = tid >> 5;
    const int lane = tid & 31;

    const __nv_bfloat16* Qbh = g_Qh + (size_t)b * CKD * NN;
    const __nv_bfloat16* Qbl = g_Ql + (size_t)b * CKD * NN;
    const __nv_bfloat16* Kbh = g_Kh + (size_t)b * CKD * NN;
    const __nv_bfloat16* Kbl = g_Kl + (size_t)b * CKD * NN;
    const __nv_bfloat16* Vbh = g_Vh + (size_t)b * CDIM * NN;
    const __nv_bfloat16* Vbl = g_Vl + (size_t)b * CDIM * NN;

    // --- cp.async issuers ---
    auto ldK = [&]() {
#pragma unroll
        for (int r = 0; r < 4; ++r) {
            int idx = tid + r * 512;
            int arr = idx >> 10, q = idx & 1023;
            int row = q >> 4, c16 = q & 15;
            uint32_t d = sb + (uint32_t)KE(arr) * 2 + row * 272 + c16 * 16;
            const __nv_bfloat16* s = (arr ? Kbl : Kbh) + (size_t)row * NN + j0g + c16 * 8;
            cp16(d, s);
        }
    };
    auto ldQ = [&](int it, int buf) {
        int i0 = it * 32;
        int arr = tid >> 8, q = tid & 255;
        int row = q >> 2, c4 = q & 3;
        uint32_t d = sb + (uint32_t)QE(buf, arr) * 2 + row * 80 + c4 * 16;
        const __nv_bfloat16* s = (arr ? Qbl : Qbh) + (size_t)row * NN + i0 + c4 * 8;
        cp16(d, s);
    };
    auto ldV = [&](int it, int buf) {
        int i0 = it * 32;
#pragma unroll
        for (int r = 0; r < 4; ++r) {
            int idx = tid + r * 512;
            int arr = idx >> 10, q = idx & 1023;
            int row = q >> 2, c4 = q & 3;
            uint32_t d = sb + (uint32_t)VE(buf, arr) * 2 + row * 80 + c4 * 16;
            const __nv_bfloat16* s = (arr ? Vbl : Vbh) + (size_t)row * NN + i0 + c4 * 8;
            cp16(d, s);
        }
    };

    // ldmatrix lane components (validated R4)
    const int l7 = lane & 7, rr = lane >> 3;
    const int a_dofs = ((rr & 2) << 2) + l7;   // A-trans: +k
    const int a_iofs = ((rr & 1) << 3);        // A-trans: +m
    const int b_kofs = ((rr & 1) << 3) + l7;   // B-trans: +k
    const int b_jofs = ((rr & 2) << 2);        // B-trans: +n
    const int v_row  = (lane & 15);            // A non-trans: +m
    const int v_col  = ((lane >> 4) << 3);     // A non-trans: +k

    // warp mappings
    const int s_i0 = (warp >> 3) * 16;         // S: 2 i-blocks (32 i total)
    const int s_j0 = (warp & 7) * 16;          // S: 8 j-blocks of 16
    const int o_c0 = (warp >> 1) * 32;         // O: 8 c-groups of 32
    const int o_j0 = (warp & 1) * 64;          // O: 2 j-groups of 64

    float oacc[16][4];
#pragma unroll
    for (int t = 0; t < 16; ++t)
#pragma unroll
        for (int e = 0; e < 4; ++e) oacc[t][e] = 0.f;

    // O(it) update: reads P[vbuf], V[vbuf]; term-major (hh, hl, lh)
    auto o_step = [&](int vbuf) {
        const uint32_t vhB = sb + (uint32_t)VE(vbuf, 0) * 2;
        const uint32_t vlB = sb + (uint32_t)VE(vbuf, 1) * 2;
        const uint32_t phB = sb + (uint32_t)PE(vbuf, 0) * 2;
        const uint32_t plB = sb + (uint32_t)PE(vbuf, 1) * 2;
#pragma unroll
        for (int k0 = 0; k0 < 32; k0 += 16) {
            uint32_t vh[2][4], vl[2][4];
#pragma unroll
            for (int ch = 0; ch < 2; ++ch) {
                uint32_t voff =
                    (uint32_t)((o_c0 + ch * 16 + v_row) * 40 + k0 + v_col) * 2;
                ldsm_x4(vh[ch], vhB + voff);
                ldsm_x4(vl[ch], vlB + voff);
            }
            uint32_t ph[4][4], pl[4][4];
#pragma unroll
            for (int jj = 0; jj < 4; ++jj) {
                uint32_t poff =
                    (uint32_t)((k0 + b_kofs) * 136 + o_j0 + jj * 16 + b_jofs) * 2;
                ldsm_x4_t(ph[jj], phB + poff);
                ldsm_x4_t(pl[jj], plB + poff);
            }
            // hh
#pragma unroll
            for (int ch = 0; ch < 2; ++ch)
#pragma unroll
                for (int jj = 0; jj < 4; ++jj) {
                    mma_bf16(oacc[ch * 8 + jj * 2 + 0], vh[ch], ph[jj] + 0);
                    mma_bf16(oacc[ch * 8 + jj * 2 + 1], vh[ch], ph[jj] + 2);
                }
            // hl
#pragma unroll
            for (int ch = 0; ch < 2; ++ch)
#pragma unroll
                for (int jj = 0; jj < 4; ++jj) {
                    mma_bf16(oacc[ch * 8 + jj * 2 + 0], vh[ch], pl[jj] + 0);
                    mma_bf16(oacc[ch * 8 + jj * 2 + 1], vh[ch], pl[jj] + 2);
                }
            // lh
#pragma unroll
            for (int ch = 0; ch < 2; ++ch)
#pragma unroll
                for (int jj = 0; jj < 4; ++jj) {
                    mma_bf16(oacc[ch * 8 + jj * 2 + 0], vl[ch], ph[jj] + 0);
                    mma_bf16(oacc[ch * 8 + jj * 2 + 1], vl[ch], ph[jj] + 2);
                }
        }
    };

    // prologue: K + Q(0)
    ldK();
    ldQ(0, 0);
    cp_commit();
    cp_wait<0>();
    __syncthreads();

    const uint32_t khB = sb + (uint32_t)KE(0) * 2;
    const uint32_t klB = sb + (uint32_t)KE(1) * 2;

    for (int it = 0; it < 128; ++it) {
        const int buf = it & 1;

        // async loads for the pipeline
        if (it < 127) ldQ(it + 1, buf ^ 1);
        ldV(it, buf);
        cp_commit();

        // ---- S(it) = Q^T K  (warp: 16i x 16j), term-major ----
        float sacc[2][4];
#pragma unroll
        for (int t = 0; t < 2; ++t)
#pragma unroll
            for (int e = 0; e < 4; ++e) sacc[t][e] = 0.f;

        const uint32_t qhB = sb + (uint32_t)QE(buf, 0) * 2;
        const uint32_t qlB = sb + (uint32_t)QE(buf, 1) * 2;
#pragma unroll
        for (int k0 = 0; k0 < 64; k0 += 16) {
            uint32_t ah[4], al[4], bh[4], bl[4];
            uint32_t aoff = (uint32_t)((k0 + a_dofs) * 40 + s_i0 + a_iofs) * 2;
            ldsm_x4_t(ah, qhB + aoff);
            ldsm_x4_t(al, qlB + aoff);
            uint32_t boff = (uint32_t)((k0 + b_kofs) * 136 + s_j0 + b_jofs) * 2;
            ldsm_x4_t(bh, khB + boff);
            ldsm_x4_t(bl, klB + boff);
            mma_bf16(sacc[0], ah, bh + 0);
            mma_bf16(sacc[1], ah, bh + 2);
            mma_bf16(sacc[0], ah, bl + 0);
            mma_bf16(sacc[1], ah, bl + 2);
            mma_bf16(sacc[0], al, bh + 0);
            mma_bf16(sacc[1], al, bh + 2);
        }

        // ---- P(it) = elu(S)/N, split hi/lo -> P[buf] ----
        {
            int prow = s_i0 + (lane >> 2);
            int pcol = s_j0 + (lane & 3) * 2;
            __nv_bfloat16* Ph = smb + PE(buf, 0);
            __nv_bfloat16* Pl = smb + PE(buf, 1);
#pragma unroll
            for (int nt = 0; nt < 2; ++nt) {
                int jc = pcol + nt * 8;
                float p0 = elu_scaled(sacc[nt][0]);
                float p1 = elu_scaled(sacc[nt][1]);
                float p2 = elu_scaled(sacc[nt][2]);
                float p3 = elu_scaled(sacc[nt][3]);
                __nv_bfloat16 h0, l0, h1, l1;
                __nv_bfloat162 th, tl;
                split2(p0, h0, l0); split2(p1, h1, l1);
                th.x = h0; th.y = h1; tl.x = l0; tl.y = l1;
                *(__nv_bfloat162*)&Ph[prow * 136 + jc] = th;
                *(__nv_bfloat162*)&Pl[prow * 136 + jc] = tl;
                split2(p2, h0, l0); split2(p3, h1, l1);
                th.x = h0; th.y = h1; tl.x = l0; tl.y = l1;
                *(__nv_bfloat162*)&Ph[(prow + 8) * 136 + jc] = th;
                *(__nv_bfloat162*)&Pl[(prow + 8) * 136 + jc] = tl;
            }
        }

        // ---- O(it-1) += V(it-1) P(it-1)  (independent of S(it)) ----
        if (it > 0) o_step(buf ^ 1);

        cp_wait<0>();
        __syncthreads();
    }

    // final O(127): buf 1
    o_step(1);

    // ---- store O accumulators, split bf16, to scratch ----
#pragma unroll
    for (int cb = 0; cb < 2; ++cb) {
        int orow = o_c0 + cb * 16 + (lane >> 2);
#pragma unroll
        for (int jj = 0; jj < 4; ++jj) {
#pragma unroll
            for (int h = 0; h < 2; ++h) {
                float* a = oacc[cb * 8 + jj * 2 + h];
                int col = j0g + o_j0 + jj * 16 + h * 8 + (lane & 3) * 2;
                size_t i0 = ((size_t)b * CDIM + orow) * NN + col;
                size_t i1 = ((size_t)b * CDIM + orow + 8) * NN + col;
                __nv_bfloat16 h0, l0, h1, l1;
                __nv_bfloat162 th, tl;
                split2(a[0], h0, l0); split2(a[1], h1, l1);
                th.x = h0; th.y = h1; tl.x = l0; tl.y = l1;
                *(__nv_bfloat162*)&g_Oh[i0] = th;
                *(__nv_bfloat162*)&g_Ol[i0] = tl;
                split2(a[2], h0, l0); split2(a[3], h1, l1);
                th.x = h0; th.y = h1; tl.x = l0; tl.y = l1;
                *(__nv_bfloat162*)&g_Oh[i1] = th;
                *(__nv_bfloat162*)&g_Ol[i1] = tl;
            }
        }
    }
}

// ---------------------------------------------------------------------------
extern "C" void kernel_launch(void* const* d_in, const int* in_sizes, int n_in,
                              void* d_out, int out_size)
{
    const float* x  = (const float*)d_in[0];
    const float* wq = (const float*)d_in[1];
    const float* bq = (const float*)d_in[2];
    const float* wk = (const float*)d_in[3];
    const float* bk = (const float*)d_in[4];
    const float* wv = (const float*)d_in[5];
    const float* bv = (const float*)d_in[6];
    const float* wg = (const float*)d_in[7];
    const float* bg = (const float*)d_in[8];
    float* out = (float*)d_out;

    __nv_bfloat16 *xh, *xl, *Qh, *Ql, *Kh, *Kl, *Vh, *Vl, *Oh, *Ol;
    __nv_bfloat16 *Wqh, *Wql, *Wkh, *Wkl, *Wvh, *Wvl, *Wgh, *Wgl;
    cudaGetSymbolAddress((void**)&xh, g_xh);
    cudaGetSymbolAddress((void**)&xl, g_xl);
    cudaGetSymbolAddress((void**)&Qh, g_Qh);
    cudaGetSymbolAddress((void**)&Ql, g_Ql);
    cudaGetSymbolAddress((void**)&Kh, g_Kh);
    cudaGetSymbolAddress((void**)&Kl, g_Kl);
    cudaGetSymbolAddress((void**)&Vh, g_Vh);
    cudaGetSymbolAddress((void**)&Vl, g_Vl);
    cudaGetSymbolAddress((void**)&Oh, g_Oh);
    cudaGetSymbolAddress((void**)&Ol, g_Ol);
    cudaGetSymbolAddress((void**)&Wqh, g_Wqh);
    cudaGetSymbolAddress((void**)&Wql, g_Wql);
    cudaGetSymbolAddress((void**)&Wkh, g_Wkh);
    cudaGetSymbolAddress((void**)&Wkl, g_Wkl);
    cudaGetSymbolAddress((void**)&Wvh, g_Wvh);
    cudaGetSymbolAddress((void**)&Wvl, g_Wvl);
    cudaGetSymbolAddress((void**)&Wgh, g_Wgh);
    cudaGetSymbolAddress((void**)&Wgl, g_Wgl);

    const int smem_attn = SM_ATTN_EL * 2;   // 172032 bytes
    cudaFuncSetAttribute(attn_bf16_kernel, cudaFuncAttributeMaxDynamicSharedMemorySize,
                         smem_attn);
    const int smem_proj = (2 * 64 * WLD + 2 * 2 * 64 * XLD) * 2;
    cudaFuncSetAttribute(proj_mma_kernel, cudaFuncAttributeMaxDynamicSharedMemorySize,
                         smem_proj);

    // 1. split x and weights -> bf16 hi/lo
    const int n4x = NB * CDIM * NN / 4;
    split_kernel<<<(n4x + 255) / 256, 256>>>(
        (const float4*)x, (__nv_bfloat162*)xh, (__nv_bfloat162*)xl, n4x);
    const int n4s = CKD * CDIM / 4, n4b = CDIM * CDIM / 4;
    split_kernel<<<(n4s + 255) / 256, 256>>>(
        (const float4*)wq, (__nv_bfloat162*)Wqh, (__nv_bfloat162*)Wql, n4s);
    split_kernel<<<(n4s + 255) / 256, 256>>>(
        (const float4*)wk, (__nv_bfloat162*)Wkh, (__nv_bfloat162*)Wkl, n4s);
    split_kernel<<<(n4b + 255) / 256, 256>>>(
        (const float4*)wv, (__nv_bfloat162*)Wvh, (__nv_bfloat162*)Wvl, n4b);
    split_kernel<<<(n4b + 255) / 256, 256>>>(
        (const float4*)wg, (__nv_bfloat162*)Wgh, (__nv_bfloat162*)Wgl, n4b);

    // 2. QKV projections on tensor cores (split bf16 out)
    proj_mma_kernel<<<dim3(NN / 128, CKD / 64, NB), 256, smem_proj>>>(
        Wqh, Wql, bq, xh, xl, Qh, Ql, nullptr, CKD);
    proj_mma_kernel<<<dim3(NN / 128, CKD / 64, NB), 256, smem_proj>>>(
        Wkh, Wkl, bk, xh, xl, Kh, Kl, nullptr, CKD);
    proj_mma_kernel<<<dim3(NN / 128, CDIM / 64, NB), 256, smem_proj>>>(
        Wvh, Wvl, bv, xh, xl, Vh, Vl, nullptr, CDIM);

    // 3. Fused attention (energy never materialized), split bf16 out
    attn_bf16_kernel<<<dim3(NN / 128, NB), 512, smem_attn>>>();

    // 4. Final 1x1 conv (wg) -> fp32 output
    proj_mma_kernel<<<dim3(NN / 128, CDIM / 64, NB), 256, smem_proj>>>(
        Wgh, Wgl, bg, Oh, Ol, nullptr, nullptr, out, CDIM);
}